// round 6
// baseline (speedup 1.0000x reference)
#include <cuda_runtime.h>
#include <cuda_fp16.h>
#include <cstdint>

// ============================================================================
// PackedBitLinear: out[8192,4096] = x[8192,4096] @ W^T, W = (unpack2bit-1)*scale
// Key identity: the abs-max scaling in the reference cancels exactly:
//   (x/s) @ W^T * s == x @ W^T   (same scalar per row divides then multiplies)
// So we compute a plain GEMM. Ternary weights are EXACT in fp16; x->fp16
// rounding gives ~2.8e-4 norm rel-err with fp32 accumulation.
//
// Pipeline:
//   1. convert_x : fp32 x -> fp16 XH            (vectorized, 192MB traffic)
//   2. decode_w  : packed int32 -> fp16 WH      (ternary-1, 36MB traffic)
//   3. gemm      : 128x128x32 tiles, cp.async 4-stage pipeline,
//                  mma.sync.m16n8k16 f32.f16.f16.f32, epilogue * scale
// ============================================================================

#define TOKENS 8192
#define NF 4096
#define KF 4096

#define BM 128
#define BN 128
#define BK 32
#define LDSH 40                 // padded row stride in halves (80B) -> LDSM conflict-free
#define STAGES 4
#define A_ELEMS (BM * LDSH)     // 5120 halves
#define STAGE_ELEMS (2 * A_ELEMS)
#define KT (KF / BK)            // 128

static __device__ __half g_XH[(size_t)TOKENS * KF];   // 64 MB scratch
static __device__ __half g_WH[(size_t)NF * KF];       // 32 MB scratch

// ---------------------------------------------------------------------------
// Kernel 1: x fp32 -> fp16 (8 elems / thread, 16B loads + 16B stores)
// ---------------------------------------------------------------------------
__global__ void __launch_bounds__(256) convert_x_kernel(const float* __restrict__ x) {
    size_t i = (size_t)blockIdx.x * blockDim.x + threadIdx.x;   // 8-element chunk
    const float4* p = reinterpret_cast<const float4*>(x) + 2 * i;
    float4 a = p[0];
    float4 b = p[1];
    __half2 h0 = __floats2half2_rn(a.x, a.y);
    __half2 h1 = __floats2half2_rn(a.z, a.w);
    __half2 h2 = __floats2half2_rn(b.x, b.y);
    __half2 h3 = __floats2half2_rn(b.z, b.w);
    uint4 u;
    u.x = *reinterpret_cast<uint32_t*>(&h0);
    u.y = *reinterpret_cast<uint32_t*>(&h1);
    u.z = *reinterpret_cast<uint32_t*>(&h2);
    u.w = *reinterpret_cast<uint32_t*>(&h3);
    reinterpret_cast<uint4*>(g_XH)[i] = u;
}

// ---------------------------------------------------------------------------
// Kernel 2: packed 2-bit ternary -> fp16 {-1,0,1}. One int32 -> 16 halves (32B).
// Bit j*2..j*2+1 holds val_j in {0,1,2}; element index within row = pk*16 + j.
// ---------------------------------------------------------------------------
__global__ void __launch_bounds__(256) decode_w_kernel(const int* __restrict__ pw) {
    size_t i = (size_t)blockIdx.x * blockDim.x + threadIdx.x;   // one packed int32
    int p = pw[i];
    uint32_t r[8];
#pragma unroll
    for (int j2 = 0; j2 < 8; j2++) {
        int v0 = ((p >> (4 * j2)) & 3) - 1;       // element 2*j2
        int v1 = ((p >> (4 * j2 + 2)) & 3) - 1;   // element 2*j2+1
        __half2 h = __halves2half2(__int2half_rn(v0), __int2half_rn(v1)); // low=first
        r[j2] = *reinterpret_cast<uint32_t*>(&h);
    }
    uint4* dst = reinterpret_cast<uint4*>(g_WH + i * 16);
    dst[0] = make_uint4(r[0], r[1], r[2], r[3]);
    dst[1] = make_uint4(r[4], r[5], r[6], r[7]);
}

// ---------------------------------------------------------------------------
// Kernel 3: GEMM
// ---------------------------------------------------------------------------
__device__ __forceinline__ void ldsm_x4(uint32_t (&r)[4], uint32_t addr) {
    asm volatile("ldmatrix.sync.aligned.m8n8.x4.shared.b16 {%0,%1,%2,%3}, [%4];\n"
                 : "=r"(r[0]), "=r"(r[1]), "=r"(r[2]), "=r"(r[3]) : "r"(addr));
}

__device__ __forceinline__ void mma16816(float (&c)[4], const uint32_t (&a)[4],
                                         uint32_t b0, uint32_t b1) {
    asm volatile(
        "mma.sync.aligned.m16n8k16.row.col.f32.f16.f16.f32 "
        "{%0,%1,%2,%3},{%4,%5,%6,%7},{%8,%9},{%0,%1,%2,%3};\n"
        : "+f"(c[0]), "+f"(c[1]), "+f"(c[2]), "+f"(c[3])
        : "r"(a[0]), "r"(a[1]), "r"(a[2]), "r"(a[3]), "r"(b0), "r"(b1));
}

#define CP_ASYNC16(dst, src) \
    asm volatile("cp.async.cg.shared.global [%0], [%1], 16;\n" :: "r"(dst), "l"(src))
#define CP_COMMIT() asm volatile("cp.async.commit_group;\n" ::: "memory")
#define CP_WAIT(n)  asm volatile("cp.async.wait_group %0;\n" :: "n"(n) : "memory")

__device__ __forceinline__ void load_stage(__half* smem, int stage, int kt,
                                           int bm0, int bn0, int tid) {
    const int k0 = kt * BK;
    __half* sA = smem + stage * STAGE_ELEMS;
    __half* sB = sA + A_ELEMS;
#pragma unroll
    for (int t = 0; t < 2; t++) {
        int c = tid + t * 256;       // 512 16B-chunks per tile
        int row = c >> 2;
        int kc = (c & 3) << 3;       // halves
        const __half* ga = g_XH + (size_t)(bm0 + row) * KF + k0 + kc;
        uint32_t da = (uint32_t)__cvta_generic_to_shared(sA + row * LDSH + kc);
        CP_ASYNC16(da, ga);
        const __half* gb = g_WH + (size_t)(bn0 + row) * KF + k0 + kc;
        uint32_t db = (uint32_t)__cvta_generic_to_shared(sB + row * LDSH + kc);
        CP_ASYNC16(db, gb);
    }
}

__global__ void __launch_bounds__(256, 1) gemm_kernel(float* __restrict__ out,
                                                      const float* __restrict__ scale) {
    extern __shared__ __half smem[];
    const int tid = threadIdx.x;
    const int lane = tid & 31;
    const int warp = tid >> 5;
    const int wm = warp & 3;          // 4 warps in M
    const int wn = warp >> 2;         // 2 warps in N
    const int bn0 = blockIdx.x * BN;
    const int bm0 = blockIdx.y * BM;

    float acc[2][8][4];
#pragma unroll
    for (int i = 0; i < 2; i++)
#pragma unroll
        for (int j = 0; j < 8; j++)
#pragma unroll
            for (int k = 0; k < 4; k++) acc[i][j][k] = 0.0f;

    // prologue: fill STAGES-1 stages
#pragma unroll
    for (int s = 0; s < STAGES - 1; s++) {
        load_stage(smem, s, s, bm0, bn0, tid);
        CP_COMMIT();
    }
    CP_WAIT(STAGES - 2);
    __syncthreads();

    for (int kt = 0; kt < KT; kt++) {
        __half* sA = smem + (kt & (STAGES - 1)) * STAGE_ELEMS;
        __half* sB = sA + A_ELEMS;

#pragma unroll
        for (int kk = 0; kk < BK; kk += 16) {
            uint32_t a[2][4];
#pragma unroll
            for (int am = 0; am < 2; am++) {
                int row = wm * 32 + am * 16 + (lane & 15);
                int k = kk + ((lane >> 4) << 3);
                uint32_t addr = (uint32_t)__cvta_generic_to_shared(sA + row * LDSH + k);
                ldsm_x4(a[am], addr);
            }
#pragma unroll
            for (int p = 0; p < 4; p++) {
                uint32_t b[4];
                int sel = lane >> 3;
                int n = wn * 64 + p * 16 + (lane & 7) + ((sel >> 1) << 3);
                int k = kk + ((sel & 1) << 3);
                uint32_t addr = (uint32_t)__cvta_generic_to_shared(sB + n * LDSH + k);
                ldsm_x4(b, addr);
#pragma unroll
                for (int am = 0; am < 2; am++) {
                    mma16816(acc[am][2 * p],     a[am], b[0], b[1]);
                    mma16816(acc[am][2 * p + 1], a[am], b[2], b[3]);
                }
            }
        }

        int nk = kt + STAGES - 1;
        if (nk < KT) load_stage(smem, nk & (STAGES - 1), nk, bm0, bn0, tid);
        CP_COMMIT();
        CP_WAIT(STAGES - 2);
        __syncthreads();
    }

    // epilogue
    const float s = __ldg(scale);
#pragma unroll
    for (int am = 0; am < 2; am++) {
#pragma unroll
        for (int bn = 0; bn < 8; bn++) {
            int row0 = bm0 + wm * 32 + am * 16 + (lane >> 2);
            int col = bn0 + wn * 64 + bn * 8 + ((lane & 3) << 1);
            float2 v0 = make_float2(acc[am][bn][0] * s, acc[am][bn][1] * s);
            float2 v1 = make_float2(acc[am][bn][2] * s, acc[am][bn][3] * s);
            *reinterpret_cast<float2*>(out + (size_t)row0 * NF + col) = v0;
            *reinterpret_cast<float2*>(out + (size_t)(row0 + 8) * NF + col) = v1;
        }
    }
}

// ---------------------------------------------------------------------------
extern "C" void kernel_launch(void* const* d_in, const int* in_sizes, int n_in,
                              void* d_out, int out_size) {
    const float* x     = (const float*)d_in[0];
    const int*   pw    = (const int*)d_in[1];
    const float* scale = (const float*)d_in[2];
    float*       out   = (float*)d_out;

    // 1) x fp32 -> fp16
    {
        size_t chunks = (size_t)TOKENS * KF / 8;            // 4,194,304
        convert_x_kernel<<<(unsigned)(chunks / 256), 256>>>(x);
    }
    // 2) decode weights
    {
        size_t ints = (size_t)NF * KF / 16;                 // 1,048,576
        decode_w_kernel<<<(unsigned)(ints / 256), 256>>>(pw);
    }
    // 3) GEMM
    {
        size_t smem_bytes = (size_t)STAGE_ELEMS * STAGES * sizeof(__half); // 81920
        cudaFuncSetAttribute(gemm_kernel, cudaFuncAttributeMaxDynamicSharedMemorySize,
                             (int)smem_bytes);
        dim3 grid(NF / BN, TOKENS / BM);                    // 32 x 64
        gemm_kernel<<<grid, 256, smem_bytes>>>(out, scale);
    }
}